// round 1
// baseline (speedup 1.0000x reference)
#include <cuda_runtime.h>

#define DIMN   256
#define NHEAD  8
#define HD     32
#define BB     8
#define NQ     512
#define NK     4096
#define SCALE  0.17677669529663687f  /* 32^-0.5 */

// Scratch (device globals: allocation-free per harness rules)
__device__ float g_q [BB * NQ * DIMN];            // 4 MB   [b, nq, h*HD+d]
__device__ float g_k [BB * NHEAD * NK * HD];      // 33.5MB [b,h,nk,d]
__device__ float g_v [BB * NHEAD * NK * HD];      // 33.5MB [b,h,nk,d]
__device__ float g_ao[BB * NQ * DIMN];            // 4 MB   [b, nq, h*HD+d]

// ---------------------------------------------------------------------------
// Generic fp32 GEMM body: C[M,N] = A[M,K] @ W[K,N] + bias[N]
// 64x64 block tile, 256 threads, 4x4 micro-tile, K-tile 16.
// Requires M%64==0, N%64==0, K%16==0, 16B-aligned rows.
// ---------------------------------------------------------------------------
__device__ __forceinline__ void gemm_body(const float* __restrict__ A,
                                          const float* __restrict__ W,
                                          const float* __restrict__ bias,
                                          float* __restrict__ C,
                                          int M, int N, int K)
{
    __shared__ float As[16][68];
    __shared__ float Ws[16][68];
    const int tx = threadIdx.x & 15;
    const int ty = threadIdx.x >> 4;
    const int m0 = blockIdx.y * 64;
    const int n0 = blockIdx.x * 64;

    const int ar = threadIdx.x >> 2;        // 0..63
    const int ac = (threadIdx.x & 3) * 4;   // 0,4,8,12

    float acc[4][4] = {};

    for (int k0 = 0; k0 < K; k0 += 16) {
        float4 av = *(const float4*)&A[(size_t)(m0 + ar) * K + k0 + ac];
        As[ac + 0][ar] = av.x;
        As[ac + 1][ar] = av.y;
        As[ac + 2][ar] = av.z;
        As[ac + 3][ar] = av.w;
        float4 wv = *(const float4*)&W[(size_t)(k0 + ty) * N + n0 + tx * 4];
        *(float4*)&Ws[ty][tx * 4] = wv;
        __syncthreads();
        #pragma unroll
        for (int k = 0; k < 16; k++) {
            float4 a4 = *(const float4*)&As[k][ty * 4];
            float4 w4 = *(const float4*)&Ws[k][tx * 4];
            float ai[4] = {a4.x, a4.y, a4.z, a4.w};
            float wj[4] = {w4.x, w4.y, w4.z, w4.w};
            #pragma unroll
            for (int i = 0; i < 4; i++)
                #pragma unroll
                for (int j = 0; j < 4; j++)
                    acc[i][j] += ai[i] * wj[j];
        }
        __syncthreads();
    }

    #pragma unroll
    for (int i = 0; i < 4; i++) {
        float4 o;
        o.x = acc[i][0] + bias[n0 + tx * 4 + 0];
        o.y = acc[i][1] + bias[n0 + tx * 4 + 1];
        o.z = acc[i][2] + bias[n0 + tx * 4 + 2];
        o.w = acc[i][3] + bias[n0 + tx * 4 + 3];
        *(float4*)&C[(size_t)(m0 + ty * 4 + i) * N + n0 + tx * 4] = o;
    }
}

__global__ __launch_bounds__(256) void gemm_q(const float* __restrict__ A,
                                              const float* __restrict__ W,
                                              const float* __restrict__ bias)
{
    gemm_body(A, W, bias, g_q, BB * NQ, DIMN, DIMN);
}

__global__ __launch_bounds__(256) void gemm_out(const float* __restrict__ W,
                                                const float* __restrict__ bias,
                                                float* __restrict__ C)
{
    gemm_body(g_ao, W, bias, C, BB * NQ, DIMN, DIMN);
}

// KV projection: A = pointcloud [B*NK, 256], W = Wkv [256, 512].
// Epilogue scatters columns [0,256) -> g_k[b,h,nk,d], [256,512) -> g_v.
__global__ __launch_bounds__(256) void gemm_kv(const float* __restrict__ A,
                                               const float* __restrict__ W,
                                               const float* __restrict__ bias)
{
    const int M = BB * NK, N = 2 * DIMN, K = DIMN;
    __shared__ float As[16][68];
    __shared__ float Ws[16][68];
    const int tx = threadIdx.x & 15;
    const int ty = threadIdx.x >> 4;
    const int m0 = blockIdx.y * 64;
    const int n0 = blockIdx.x * 64;

    const int ar = threadIdx.x >> 2;
    const int ac = (threadIdx.x & 3) * 4;

    float acc[4][4] = {};

    for (int k0 = 0; k0 < K; k0 += 16) {
        float4 av = *(const float4*)&A[(size_t)(m0 + ar) * K + k0 + ac];
        As[ac + 0][ar] = av.x;
        As[ac + 1][ar] = av.y;
        As[ac + 2][ar] = av.z;
        As[ac + 3][ar] = av.w;
        float4 wv = *(const float4*)&W[(size_t)(k0 + ty) * N + n0 + tx * 4];
        *(float4*)&Ws[ty][tx * 4] = wv;
        __syncthreads();
        #pragma unroll
        for (int k = 0; k < 16; k++) {
            float4 a4 = *(const float4*)&As[k][ty * 4];
            float4 w4 = *(const float4*)&Ws[k][tx * 4];
            float ai[4] = {a4.x, a4.y, a4.z, a4.w};
            float wj[4] = {w4.x, w4.y, w4.z, w4.w};
            #pragma unroll
            for (int i = 0; i < 4; i++)
                #pragma unroll
                for (int j = 0; j < 4; j++)
                    acc[i][j] += ai[i] * wj[j];
        }
        __syncthreads();
    }

    const int gc = n0 + tx * 4;             // 4-aligned, never crosses a 32-group
    #pragma unroll
    for (int i = 0; i < 4; i++) {
        const int gm = m0 + ty * 4 + i;
        const int b  = gm >> 12;            // /4096
        const int nk = gm & (NK - 1);
        float4 o;
        o.x = acc[i][0] + bias[gc + 0];
        o.y = acc[i][1] + bias[gc + 1];
        o.z = acc[i][2] + bias[gc + 2];
        o.w = acc[i][3] + bias[gc + 3];
        float* dst;
        if (gc < DIMN) {
            const int h = gc >> 5, d = gc & 31;
            dst = &g_k[(((size_t)(b * NHEAD + h)) * NK + nk) * HD + d];
        } else {
            const int c = gc - DIMN;
            const int h = c >> 5, d = c & 31;
            dst = &g_v[(((size_t)(b * NHEAD + h)) * NK + nk) * HD + d];
        }
        *(float4*)dst = o;
    }
}

// ---------------------------------------------------------------------------
// Flash attention: one block per (q-tile of 64, h, b). 256 threads.
// S = (Q*SCALE) @ K^T  [64x64 tile], online softmax, O += P @ V.
// ---------------------------------------------------------------------------
__global__ __launch_bounds__(256) void attn_kernel()
{
    __shared__ float Qs[HD][68];    // [d][q]
    __shared__ float Ks[HD][68];    // [d][k]
    __shared__ float Vs[64][36];    // [k][d]
    __shared__ float Ps[64][68];    // [q][k]

    const int tx = threadIdx.x & 15;
    const int ty = threadIdx.x >> 4;
    const int q0 = blockIdx.x * 64;
    const int h  = blockIdx.y;
    const int b  = blockIdx.z;
    const int bh = b * NHEAD + h;

    // Load + transpose + scale Q tile [64 x 32]
    {
        const int e   = threadIdx.x * 8;
        const int row = e >> 5;
        const int d   = e & 31;
        const float* qp = &g_q[((size_t)(b * NQ + q0 + row)) * DIMN + h * HD + d];
        float4 q1 = *(const float4*)qp;
        float4 q2 = *(const float4*)(qp + 4);
        Qs[d + 0][row] = q1.x * SCALE;
        Qs[d + 1][row] = q1.y * SCALE;
        Qs[d + 2][row] = q1.z * SCALE;
        Qs[d + 3][row] = q1.w * SCALE;
        Qs[d + 4][row] = q2.x * SCALE;
        Qs[d + 5][row] = q2.y * SCALE;
        Qs[d + 6][row] = q2.z * SCALE;
        Qs[d + 7][row] = q2.w * SCALE;
    }

    float m_r[4], l_r[4], o[4][2];
    #pragma unroll
    for (int i = 0; i < 4; i++) {
        m_r[i] = -1e30f;
        l_r[i] = 0.f;
        o[i][0] = 0.f;
        o[i][1] = 0.f;
    }

    const float* kbase = &g_k[(size_t)bh * NK * HD];
    const float* vbase = &g_v[(size_t)bh * NK * HD];

    for (int k0 = 0; k0 < NK; k0 += 64) {
        __syncthreads();   // protect Ks/Vs/Ps reuse from previous iteration
        {
            const int e   = threadIdx.x * 8;
            const int row = e >> 5;
            const int d   = e & 31;
            const float* kp = kbase + (size_t)(k0 + row) * HD + d;
            float4 k1 = *(const float4*)kp;
            float4 k2 = *(const float4*)(kp + 4);
            Ks[d + 0][row] = k1.x; Ks[d + 1][row] = k1.y;
            Ks[d + 2][row] = k1.z; Ks[d + 3][row] = k1.w;
            Ks[d + 4][row] = k2.x; Ks[d + 5][row] = k2.y;
            Ks[d + 6][row] = k2.z; Ks[d + 7][row] = k2.w;
            const float* vp = vbase + (size_t)(k0 + row) * HD + d;
            *(float4*)&Vs[row][d]     = *(const float4*)vp;
            *(float4*)&Vs[row][d + 4] = *(const float4*)(vp + 4);
        }
        __syncthreads();

        // S tile: 4x4 per thread
        float s[4][4] = {};
        #pragma unroll
        for (int d = 0; d < HD; d++) {
            float4 q4 = *(const float4*)&Qs[d][ty * 4];
            float4 k4 = *(const float4*)&Ks[d][tx * 4];
            float qi[4] = {q4.x, q4.y, q4.z, q4.w};
            float kj[4] = {k4.x, k4.y, k4.z, k4.w};
            #pragma unroll
            for (int i = 0; i < 4; i++)
                #pragma unroll
                for (int j = 0; j < 4; j++)
                    s[i][j] += qi[i] * kj[j];
        }

        // Online softmax (row reduction over the 16 tx lanes, intra-warp)
        #pragma unroll
        for (int i = 0; i < 4; i++) {
            float mt = fmaxf(fmaxf(s[i][0], s[i][1]), fmaxf(s[i][2], s[i][3]));
            #pragma unroll
            for (int off = 8; off >= 1; off >>= 1)
                mt = fmaxf(mt, __shfl_xor_sync(0xffffffffu, mt, off));
            const float mn   = fmaxf(m_r[i], mt);
            const float corr = __expf(m_r[i] - mn);
            float p0 = __expf(s[i][0] - mn);
            float p1 = __expf(s[i][1] - mn);
            float p2 = __expf(s[i][2] - mn);
            float p3 = __expf(s[i][3] - mn);
            float4 pv = {p0, p1, p2, p3};
            *(float4*)&Ps[ty * 4 + i][tx * 4] = pv;
            float rs = (p0 + p1) + (p2 + p3);
            #pragma unroll
            for (int off = 8; off >= 1; off >>= 1)
                rs += __shfl_xor_sync(0xffffffffu, rs, off);
            l_r[i]  = l_r[i] * corr + rs;
            o[i][0] *= corr;
            o[i][1] *= corr;
            m_r[i]  = mn;
        }
        __syncthreads();

        // O += P @ V  (4 rows x 2 cols per thread)
        #pragma unroll
        for (int kk = 0; kk < 64; kk += 4) {
            float4 p0 = *(const float4*)&Ps[ty * 4 + 0][kk];
            float4 p1 = *(const float4*)&Ps[ty * 4 + 1][kk];
            float4 p2 = *(const float4*)&Ps[ty * 4 + 2][kk];
            float4 p3 = *(const float4*)&Ps[ty * 4 + 3][kk];
            float2 v0 = *(const float2*)&Vs[kk + 0][tx * 2];
            float2 v1 = *(const float2*)&Vs[kk + 1][tx * 2];
            float2 v2 = *(const float2*)&Vs[kk + 2][tx * 2];
            float2 v3 = *(const float2*)&Vs[kk + 3][tx * 2];
            o[0][0] += p0.x * v0.x + p0.y * v1.x + p0.z * v2.x + p0.w * v3.x;
            o[0][1] += p0.x * v0.y + p0.y * v1.y + p0.z * v2.y + p0.w * v3.y;
            o[1][0] += p1.x * v0.x + p1.y * v1.x + p1.z * v2.x + p1.w * v3.x;
            o[1][1] += p1.x * v0.y + p1.y * v1.y + p1.z * v2.y + p1.w * v3.y;
            o[2][0] += p2.x * v0.x + p2.y * v1.x + p2.z * v2.x + p2.w * v3.x;
            o[2][1] += p2.x * v0.y + p2.y * v1.y + p2.z * v2.y + p2.w * v3.y;
            o[3][0] += p3.x * v0.x + p3.y * v1.x + p3.z * v2.x + p3.w * v3.x;
            o[3][1] += p3.x * v0.y + p3.y * v1.y + p3.z * v2.y + p3.w * v3.y;
        }
    }

    #pragma unroll
    for (int i = 0; i < 4; i++) {
        const float inv = 1.0f / l_r[i];
        float2 ov = {o[i][0] * inv, o[i][1] * inv};
        *(float2*)&g_ao[((size_t)(b * NQ + q0 + ty * 4 + i)) * DIMN
                        + h * HD + tx * 2] = ov;
    }
}

// ---------------------------------------------------------------------------
extern "C" void kernel_launch(void* const* d_in, const int* in_sizes, int n_in,
                              void* d_out, int out_size)
{
    const float* state = (const float*)d_in[0];
    const float* pc    = (const float*)d_in[1];
    const float* Wq    = (const float*)d_in[2];
    const float* bq    = (const float*)d_in[3];
    const float* Wkv   = (const float*)d_in[4];
    const float* bkv   = (const float*)d_in[5];
    const float* Wo    = (const float*)d_in[6];
    const float* bo    = (const float*)d_in[7];
    float* out = (float*)d_out;

    // Q projection: [4096,256] = state @ Wq + bq
    gemm_q<<<dim3(DIMN / 64, (BB * NQ) / 64), 256>>>(state, Wq, bq);
    // KV projection with head-arranged scatter
    gemm_kv<<<dim3((2 * DIMN) / 64, (BB * NK) / 64), 256>>>(pc, Wkv, bkv);
    // Flash attention per (q-tile, head, batch)
    attn_kernel<<<dim3(NQ / 64, NHEAD, BB), 256>>>();
    // Output projection into d_out
    gemm_out<<<dim3(DIMN / 64, (BB * NQ) / 64), 256>>>(Wo, bo, out);
}

// round 2
// speedup vs baseline: 1.0054x; 1.0054x over previous
#include <cuda_runtime.h>

#define DIMN   256
#define NHEAD  8
#define HD     32
#define BB     8
#define NQ     512
#define NK     4096
#define SCALE  0.17677669529663687f  /* 32^-0.5 */

// Scratch (device globals: allocation-free per harness rules)
__device__ float g_q [BB * NQ * DIMN];            // 4 MB   [b, nq, h*HD+d]
__device__ float g_k [BB * NHEAD * NK * HD];      // 33.5MB [b,h,nk,d]
__device__ float g_v [BB * NHEAD * NK * HD];      // 33.5MB [b,h,nk,d]
__device__ float g_ao[BB * NQ * DIMN];            // 4 MB   [b, nq, h*HD+d]

// ---------------------------------------------------------------------------
// Packed fp32x2 helpers (Blackwell FFMA2 path — ptxas never auto-emits these)
// ---------------------------------------------------------------------------
typedef unsigned long long u64;

__device__ __forceinline__ u64 pack2(float x, float y) {
    u64 u;
    asm("mov.b64 %0, {%1, %2};"
        : "=l"(u) : "r"(__float_as_uint(x)), "r"(__float_as_uint(y)));
    return u;
}
__device__ __forceinline__ u64 splat2(float x) { return pack2(x, x); }

__device__ __forceinline__ float2 unpack2(u64 u) {
    unsigned lo, hi;
    asm("mov.b64 {%0, %1}, %2;" : "=r"(lo), "=r"(hi) : "l"(u));
    return make_float2(__uint_as_float(lo), __uint_as_float(hi));
}
__device__ __forceinline__ u64 ffma2(u64 a, u64 b, u64 c) {
    u64 d;
    asm("fma.rn.f32x2 %0, %1, %2, %3;" : "=l"(d) : "l"(a), "l"(b), "l"(c));
    return d;
}
__device__ __forceinline__ u64 fmul2(u64 a, u64 b) {
    u64 d;
    asm("mul.rn.f32x2 %0, %1, %2;" : "=l"(d) : "l"(a), "l"(b));
    return d;
}

// ---------------------------------------------------------------------------
// Generic fp32 GEMM body: C[M,N] = A[M,K] @ W[K,N] + bias[N]
// 64x64 block tile, 256 threads, 4x4 micro-tile (FFMA2: 4x2 packed), K-tile 16.
// ---------------------------------------------------------------------------
__device__ __forceinline__ void gemm_body(const float* __restrict__ A,
                                          const float* __restrict__ W,
                                          const float* __restrict__ bias,
                                          float* __restrict__ C,
                                          int M, int N, int K)
{
    __shared__ float As[16][68];
    __shared__ float Ws[16][68];
    const int tx = threadIdx.x & 15;
    const int ty = threadIdx.x >> 4;
    const int m0 = blockIdx.y * 64;
    const int n0 = blockIdx.x * 64;

    const int ar = threadIdx.x >> 2;        // 0..63
    const int ac = (threadIdx.x & 3) * 4;   // 0,4,8,12

    u64 acc[4][2] = {};                     // (0,0) bit pattern == (+0.f,+0.f)

    for (int k0 = 0; k0 < K; k0 += 16) {
        float4 av = *(const float4*)&A[(size_t)(m0 + ar) * K + k0 + ac];
        As[ac + 0][ar] = av.x;
        As[ac + 1][ar] = av.y;
        As[ac + 2][ar] = av.z;
        As[ac + 3][ar] = av.w;
        float4 wv = *(const float4*)&W[(size_t)(k0 + ty) * N + n0 + tx * 4];
        *(float4*)&Ws[ty][tx * 4] = wv;
        __syncthreads();
        #pragma unroll
        for (int k = 0; k < 16; k++) {
            float4 a4 = *(const float4*)&As[k][ty * 4];
            float4 w4 = *(const float4*)&Ws[k][tx * 4];
            u64 w01 = pack2(w4.x, w4.y);
            u64 w23 = pack2(w4.z, w4.w);
            u64 s0 = splat2(a4.x), s1 = splat2(a4.y);
            u64 s2 = splat2(a4.z), s3 = splat2(a4.w);
            acc[0][0] = ffma2(s0, w01, acc[0][0]);
            acc[0][1] = ffma2(s0, w23, acc[0][1]);
            acc[1][0] = ffma2(s1, w01, acc[1][0]);
            acc[1][1] = ffma2(s1, w23, acc[1][1]);
            acc[2][0] = ffma2(s2, w01, acc[2][0]);
            acc[2][1] = ffma2(s2, w23, acc[2][1]);
            acc[3][0] = ffma2(s3, w01, acc[3][0]);
            acc[3][1] = ffma2(s3, w23, acc[3][1]);
        }
        __syncthreads();
    }

    const float4 bv = *(const float4*)&bias[n0 + tx * 4];
    #pragma unroll
    for (int i = 0; i < 4; i++) {
        float2 c01 = unpack2(acc[i][0]);
        float2 c23 = unpack2(acc[i][1]);
        float4 o;
        o.x = c01.x + bv.x;
        o.y = c01.y + bv.y;
        o.z = c23.x + bv.z;
        o.w = c23.y + bv.w;
        *(float4*)&C[(size_t)(m0 + ty * 4 + i) * N + n0 + tx * 4] = o;
    }
}

__global__ __launch_bounds__(256) void gemm_q(const float* __restrict__ A,
                                              const float* __restrict__ W,
                                              const float* __restrict__ bias)
{
    gemm_body(A, W, bias, g_q, BB * NQ, DIMN, DIMN);
}

__global__ __launch_bounds__(256) void gemm_out(const float* __restrict__ W,
                                                const float* __restrict__ bias,
                                                float* __restrict__ C)
{
    gemm_body(g_ao, W, bias, C, BB * NQ, DIMN, DIMN);
}

// KV projection: A = pointcloud [B*NK, 256], W = Wkv [256, 512].
// Epilogue scatters columns [0,256) -> g_k[b,h,nk,d], [256,512) -> g_v.
__global__ __launch_bounds__(256) void gemm_kv(const float* __restrict__ A,
                                               const float* __restrict__ W,
                                               const float* __restrict__ bias)
{
    const int N = 2 * DIMN, K = DIMN;
    __shared__ float As[16][68];
    __shared__ float Ws[16][68];
    const int tx = threadIdx.x & 15;
    const int ty = threadIdx.x >> 4;
    const int m0 = blockIdx.y * 64;
    const int n0 = blockIdx.x * 64;

    const int ar = threadIdx.x >> 2;
    const int ac = (threadIdx.x & 3) * 4;

    u64 acc[4][2] = {};

    for (int k0 = 0; k0 < K; k0 += 16) {
        float4 av = *(const float4*)&A[(size_t)(m0 + ar) * K + k0 + ac];
        As[ac + 0][ar] = av.x;
        As[ac + 1][ar] = av.y;
        As[ac + 2][ar] = av.z;
        As[ac + 3][ar] = av.w;
        float4 wv = *(const float4*)&W[(size_t)(k0 + ty) * N + n0 + tx * 4];
        *(float4*)&Ws[ty][tx * 4] = wv;
        __syncthreads();
        #pragma unroll
        for (int k = 0; k < 16; k++) {
            float4 a4 = *(const float4*)&As[k][ty * 4];
            float4 w4 = *(const float4*)&Ws[k][tx * 4];
            u64 w01 = pack2(w4.x, w4.y);
            u64 w23 = pack2(w4.z, w4.w);
            u64 s0 = splat2(a4.x), s1 = splat2(a4.y);
            u64 s2 = splat2(a4.z), s3 = splat2(a4.w);
            acc[0][0] = ffma2(s0, w01, acc[0][0]);
            acc[0][1] = ffma2(s0, w23, acc[0][1]);
            acc[1][0] = ffma2(s1, w01, acc[1][0]);
            acc[1][1] = ffma2(s1, w23, acc[1][1]);
            acc[2][0] = ffma2(s2, w01, acc[2][0]);
            acc[2][1] = ffma2(s2, w23, acc[2][1]);
            acc[3][0] = ffma2(s3, w01, acc[3][0]);
            acc[3][1] = ffma2(s3, w23, acc[3][1]);
        }
        __syncthreads();
    }

    const int gc = n0 + tx * 4;             // 4-aligned, never crosses a 32-group
    const float4 bv = *(const float4*)&bias[gc];
    #pragma unroll
    for (int i = 0; i < 4; i++) {
        const int gm = m0 + ty * 4 + i;
        const int b  = gm >> 12;            // /4096
        const int nk = gm & (NK - 1);
        float2 c01 = unpack2(acc[i][0]);
        float2 c23 = unpack2(acc[i][1]);
        float4 o;
        o.x = c01.x + bv.x;
        o.y = c01.y + bv.y;
        o.z = c23.x + bv.z;
        o.w = c23.y + bv.w;
        float* dst;
        if (gc < DIMN) {
            const int h = gc >> 5, d = gc & 31;
            dst = &g_k[(((size_t)(b * NHEAD + h)) * NK + nk) * HD + d];
        } else {
            const int c = gc - DIMN;
            const int h = c >> 5, d = c & 31;
            dst = &g_v[(((size_t)(b * NHEAD + h)) * NK + nk) * HD + d];
        }
        *(float4*)dst = o;
    }
}

// ---------------------------------------------------------------------------
// Flash attention: one block per (q-tile of 64, h, b). 256 threads.
// S = (Q*SCALE) @ K^T  [64x64 tile], online softmax, O += P @ V.
// S-tile uses FFMA2 paired along k-columns; PV uses FFMA2 paired along k
// (V stored in smem as k-pair-interleaved: Vp[kk/2][d*2 + (kk&1)]).
// ---------------------------------------------------------------------------
__global__ __launch_bounds__(256) void attn_kernel()
{
    __shared__ float Qs[HD][68];    // [d][q]
    __shared__ float Ks[HD][68];    // [d][k]
    __shared__ float Vp[32][68];    // [kpair][d*2 + parity]
    __shared__ float Ps[64][68];    // [q][k]

    const int tx = threadIdx.x & 15;
    const int ty = threadIdx.x >> 4;
    const int q0 = blockIdx.x * 64;
    const int h  = blockIdx.y;
    const int b  = blockIdx.z;
    const int bh = b * NHEAD + h;

    // Load + transpose + scale Q tile [64 x 32]
    {
        const int e   = threadIdx.x * 8;
        const int row = e >> 5;
        const int d   = e & 31;
        const float* qp = &g_q[((size_t)(b * NQ + q0 + row)) * DIMN + h * HD + d];
        float4 q1 = *(const float4*)qp;
        float4 q2 = *(const float4*)(qp + 4);
        Qs[d + 0][row] = q1.x * SCALE;
        Qs[d + 1][row] = q1.y * SCALE;
        Qs[d + 2][row] = q1.z * SCALE;
        Qs[d + 3][row] = q1.w * SCALE;
        Qs[d + 4][row] = q2.x * SCALE;
        Qs[d + 5][row] = q2.y * SCALE;
        Qs[d + 6][row] = q2.z * SCALE;
        Qs[d + 7][row] = q2.w * SCALE;
    }

    float m_r[4], l_r[4];
    u64   o2[4][2];                 // packed (even-k, odd-k) partial sums
    #pragma unroll
    for (int i = 0; i < 4; i++) {
        m_r[i] = -1e30f;
        l_r[i] = 0.f;
        o2[i][0] = 0ull;
        o2[i][1] = 0ull;
    }

    const float* kbase = &g_k[(size_t)bh * NK * HD];
    const float* vbase = &g_v[(size_t)bh * NK * HD];

    for (int k0 = 0; k0 < NK; k0 += 64) {
        __syncthreads();   // protect Ks/Vp/Ps reuse from previous iteration
        {
            const int e   = threadIdx.x * 8;
            const int row = e >> 5;
            const int d   = e & 31;
            const float* kp = kbase + (size_t)(k0 + row) * HD + d;
            float4 k1 = *(const float4*)kp;
            float4 k2 = *(const float4*)(kp + 4);
            Ks[d + 0][row] = k1.x; Ks[d + 1][row] = k1.y;
            Ks[d + 2][row] = k1.z; Ks[d + 3][row] = k1.w;
            Ks[d + 4][row] = k2.x; Ks[d + 5][row] = k2.y;
            Ks[d + 6][row] = k2.z; Ks[d + 7][row] = k2.w;
            const float* vp = vbase + (size_t)(k0 + row) * HD + d;
            float4 v1 = *(const float4*)vp;
            float4 v2 = *(const float4*)(vp + 4);
            float* vd = &Vp[row >> 1][(row & 1)];
            vd[(d + 0) * 2] = v1.x; vd[(d + 1) * 2] = v1.y;
            vd[(d + 2) * 2] = v1.z; vd[(d + 3) * 2] = v1.w;
            vd[(d + 4) * 2] = v2.x; vd[(d + 5) * 2] = v2.y;
            vd[(d + 6) * 2] = v2.z; vd[(d + 7) * 2] = v2.w;
        }
        __syncthreads();

        // S tile: 4 rows x 4 cols per thread, FFMA2 paired along cols
        u64 s2[4][2] = {};
        #pragma unroll
        for (int d = 0; d < HD; d++) {
            float4 q4 = *(const float4*)&Qs[d][ty * 4];
            float4 k4 = *(const float4*)&Ks[d][tx * 4];
            u64 k01 = pack2(k4.x, k4.y);
            u64 k23 = pack2(k4.z, k4.w);
            u64 a0 = splat2(q4.x), a1 = splat2(q4.y);
            u64 a2 = splat2(q4.z), a3 = splat2(q4.w);
            s2[0][0] = ffma2(a0, k01, s2[0][0]);
            s2[0][1] = ffma2(a0, k23, s2[0][1]);
            s2[1][0] = ffma2(a1, k01, s2[1][0]);
            s2[1][1] = ffma2(a1, k23, s2[1][1]);
            s2[2][0] = ffma2(a2, k01, s2[2][0]);
            s2[2][1] = ffma2(a2, k23, s2[2][1]);
            s2[3][0] = ffma2(a3, k01, s2[3][0]);
            s2[3][1] = ffma2(a3, k23, s2[3][1]);
        }

        // Online softmax (row reduction over the 16 tx lanes, intra-warp)
        #pragma unroll
        for (int i = 0; i < 4; i++) {
            float2 sA = unpack2(s2[i][0]);
            float2 sB = unpack2(s2[i][1]);
            float mt = fmaxf(fmaxf(sA.x, sA.y), fmaxf(sB.x, sB.y));
            #pragma unroll
            for (int off = 8; off >= 1; off >>= 1)
                mt = fmaxf(mt, __shfl_xor_sync(0xffffffffu, mt, off));
            const float mn   = fmaxf(m_r[i], mt);
            const float corr = __expf(m_r[i] - mn);
            float p0 = __expf(sA.x - mn);
            float p1 = __expf(sA.y - mn);
            float p2 = __expf(sB.x - mn);
            float p3 = __expf(sB.y - mn);
            float4 pv = {p0, p1, p2, p3};
            *(float4*)&Ps[ty * 4 + i][tx * 4] = pv;
            float rs = (p0 + p1) + (p2 + p3);
            #pragma unroll
            for (int off = 8; off >= 1; off >>= 1)
                rs += __shfl_xor_sync(0xffffffffu, rs, off);
            l_r[i]  = l_r[i] * corr + rs;
            const u64 c2 = splat2(corr);
            o2[i][0] = fmul2(o2[i][0], c2);
            o2[i][1] = fmul2(o2[i][1], c2);
            m_r[i]  = mn;
        }
        __syncthreads();

        // O += P @ V, FFMA2 paired along k.
        // Vp[m][tx*4 .. +3] = (v[2m][c0], v[2m+1][c0], v[2m][c1], v[2m+1][c1])
        #pragma unroll
        for (int kk = 0; kk < 64; kk += 4) {
            const int m = kk >> 1;
            float4 vA = *(const float4*)&Vp[m    ][tx * 4];
            float4 vB = *(const float4*)&Vp[m + 1][tx * 4];
            u64 vA0 = pack2(vA.x, vA.y);   // col c0, k-pair m
            u64 vA1 = pack2(vA.z, vA.w);   // col c1, k-pair m
            u64 vB0 = pack2(vB.x, vB.y);   // col c0, k-pair m+1
            u64 vB1 = pack2(vB.z, vB.w);   // col c1, k-pair m+1
            #pragma unroll
            for (int i = 0; i < 4; i++) {
                float4 pr = *(const float4*)&Ps[ty * 4 + i][kk];
                u64 pA = pack2(pr.x, pr.y);
                u64 pB = pack2(pr.z, pr.w);
                o2[i][0] = ffma2(pA, vA0, o2[i][0]);
                o2[i][0] = ffma2(pB, vB0, o2[i][0]);
                o2[i][1] = ffma2(pA, vA1, o2[i][1]);
                o2[i][1] = ffma2(pB, vB1, o2[i][1]);
            }
        }
    }

    #pragma unroll
    for (int i = 0; i < 4; i++) {
        const float inv = 1.0f / l_r[i];
        float2 oc0 = unpack2(o2[i][0]);
        float2 oc1 = unpack2(o2[i][1]);
        float2 ov = {(oc0.x + oc0.y) * inv, (oc1.x + oc1.y) * inv};
        *(float2*)&g_ao[((size_t)(b * NQ + q0 + ty * 4 + i)) * DIMN
                        + h * HD + tx * 2] = ov;
    }
}

// ---------------------------------------------------------------------------
extern "C" void kernel_launch(void* const* d_in, const int* in_sizes, int n_in,
                              void* d_out, int out_size)
{
    const float* state = (const float*)d_in[0];
    const float* pc    = (const float*)d_in[1];
    const float* Wq    = (const float*)d_in[2];
    const float* bq    = (const float*)d_in[3];
    const float* Wkv   = (const float*)d_in[4];
    const float* bkv   = (const float*)d_in[5];
    const float* Wo    = (const float*)d_in[6];
    const float* bo    = (const float*)d_in[7];
    float* out = (float*)d_out;

    gemm_q<<<dim3(DIMN / 64, (BB * NQ) / 64), 256>>>(state, Wq, bq);
    gemm_kv<<<dim3((2 * DIMN) / 64, (BB * NK) / 64), 256>>>(pc, Wkv, bkv);
    attn_kernel<<<dim3(NQ / 64, NHEAD, BB), 256>>>();
    gemm_out<<<dim3(DIMN / 64, (BB * NQ) / 64), 256>>>(Wo, bo, out);
}